// round 1
// baseline (speedup 1.0000x reference)
#include <cuda_runtime.h>

// Problem constants
constexpr int B_  = 32;
constexpr int H_  = 12;
constexpr int W_  = 256;
constexpr int C_  = 256;
constexpr int HS_ = 4;            // H / SPLIT
constexpr int N_  = HS_ * W_;     // 1024 flattened spatial
constexpr int FC_ = 96;           // SPLIT * Cf
constexpr int HC_ = 768;          // SPLIT * C
constexpr int P_  = B_ * H_ * W_; // 98304 pixels

// Scratch (device globals; no allocation in kernel_launch)
__device__ float g_f[(size_t)B_ * N_ * FC_];   // 12.6 MB
__device__ float g_g[(size_t)B_ * N_ * FC_];   // 12.6 MB
__device__ float g_h[(size_t)B_ * N_ * HC_];   // 100 MB
__device__ float g_s[(size_t)B_ * N_ * N_];    // 134 MB

// ---------------------------------------------------------------------------
// Kernel 1: projections. C_all[P,320] = X[P,256] @ [Wh(256)|Wf(32)|Wg(32)]
// Epilogue scatters into flattened layouts (hw_flatten).
// Tiles: BM=128 (pixels), BN=64 (cols), BK=16. 256 thr, 8x4 per thread.
// ---------------------------------------------------------------------------
__global__ __launch_bounds__(256) void k_proj(
    const float* __restrict__ x, const float* __restrict__ Wf,
    const float* __restrict__ Wg, const float* __restrict__ Wh)
{
    __shared__ float As[16][128];
    __shared__ float Bs[16][64];
    const int tid   = threadIdx.x;
    const int cBase = blockIdx.x * 64;    // 0..4  (N total = 320)
    const int pBase = blockIdx.y * 128;
    const int ty = tid >> 4, tx = tid & 15;
    const int ar  = tid >> 1;             // A-load row 0..127
    const int ak0 = (tid & 1) * 8;        // A-load k offset

    float acc[8][4];
#pragma unroll
    for (int i = 0; i < 8; i++)
#pragma unroll
        for (int j = 0; j < 4; j++) acc[i][j] = 0.f;

    for (int kT = 0; kT < 256; kT += 16) {
        // A tile: each thread 8 consecutive k from one pixel row -> transposed smem
        const float* ap = x + (size_t)(pBase + ar) * 256 + (kT + ak0);
        float4 a0 = *reinterpret_cast<const float4*>(ap);
        float4 a1 = *reinterpret_cast<const float4*>(ap + 4);
        As[ak0 + 0][ar] = a0.x; As[ak0 + 1][ar] = a0.y;
        As[ak0 + 2][ar] = a0.z; As[ak0 + 3][ar] = a0.w;
        As[ak0 + 4][ar] = a1.x; As[ak0 + 5][ar] = a1.y;
        As[ak0 + 6][ar] = a1.z; As[ak0 + 7][ar] = a1.w;
        // B tile: virtual concat [Wh | Wf | Wg]
#pragma unroll
        for (int i = 0; i < 4; i++) {
            int l  = tid + i * 256;
            int bk = l >> 6, jl = l & 63;
            int j  = cBase + jl;
            float v;
            if (j < 256)      v = Wh[(kT + bk) * 256 + j];
            else if (j < 288) v = Wf[(kT + bk) * 32 + (j - 256)];
            else              v = Wg[(kT + bk) * 32 + (j - 288)];
            Bs[bk][jl] = v;
        }
        __syncthreads();
#pragma unroll
        for (int k = 0; k < 16; k++) {
            float a[8], b[4];
#pragma unroll
            for (int i = 0; i < 8; i++) a[i] = As[k][ty * 8 + i];
#pragma unroll
            for (int j = 0; j < 4; j++) b[j] = Bs[k][tx * 4 + j];
#pragma unroll
            for (int i = 0; i < 8; i++)
#pragma unroll
                for (int j = 0; j < 4; j++)
                    acc[i][j] = fmaf(a[i], b[j], acc[i][j]);
        }
        __syncthreads();
    }

    // Epilogue: scatter to flattened buffers
#pragma unroll
    for (int i = 0; i < 8; i++) {
        int p   = pBase + ty * 8 + i;
        int b   = p / (H_ * W_);
        int rem = p - b * (H_ * W_);
        int h   = rem >> 8;       // / W_ (W_=256)
        int w   = rem & 255;
        int sg  = h >> 2;         // split group = h / hs
        int hr  = h & 3;          // h % hs
        int n   = hr * W_ + w;
#pragma unroll
        for (int jj = 0; jj < 4; jj++) {
            int   j = cBase + tx * 4 + jj;
            float v = acc[i][jj];
            if (j < 256)
                g_h[((size_t)b * N_ + n) * HC_ + sg * 256 + j] = v;
            else if (j < 288)
                g_f[((size_t)b * N_ + n) * FC_ + sg * 32 + (j - 256)] = v;
            else
                g_g[((size_t)b * N_ + n) * FC_ + sg * 32 + (j - 288)] = v;
        }
    }
}

// ---------------------------------------------------------------------------
// Kernel 2: s[b] = g_fl[b] @ f_fl[b]^T   (M=N=1024, K=96)
// Tiles: 128x128x32, 256 thr, 8x8 per thread.
// ---------------------------------------------------------------------------
__global__ __launch_bounds__(256) void k_score()
{
    __shared__ float As[32][128];
    __shared__ float Bs[32][128];
    const int tid   = threadIdx.x;
    const int b     = blockIdx.z;
    const int mBase = blockIdx.x * 128;
    const int nBase = blockIdx.y * 128;
    const int ty = tid >> 4, tx = tid & 15;

    const float* Ab = g_g + (size_t)b * N_ * FC_;
    const float* Bb = g_f + (size_t)b * N_ * FC_;

    float acc[8][8];
#pragma unroll
    for (int i = 0; i < 8; i++)
#pragma unroll
        for (int j = 0; j < 8; j++) acc[i][j] = 0.f;

    for (int kT = 0; kT < FC_; kT += 32) {
#pragma unroll
        for (int sgi = 0; sgi < 2; sgi++) {
            int sid = tid * 2 + sgi;
            int row = sid >> 2;
            int k0  = (sid & 3) * 8;
            const float* ap = Ab + (size_t)(nBase + row) * FC_ + kT + k0;
            float4 a0 = *reinterpret_cast<const float4*>(ap);
            float4 a1 = *reinterpret_cast<const float4*>(ap + 4);
            As[k0 + 0][row] = a0.x; As[k0 + 1][row] = a0.y;
            As[k0 + 2][row] = a0.z; As[k0 + 3][row] = a0.w;
            As[k0 + 4][row] = a1.x; As[k0 + 5][row] = a1.y;
            As[k0 + 6][row] = a1.z; As[k0 + 7][row] = a1.w;
            const float* bp = Bb + (size_t)(mBase + row) * FC_ + kT + k0;
            float4 b0 = *reinterpret_cast<const float4*>(bp);
            float4 b1 = *reinterpret_cast<const float4*>(bp + 4);
            Bs[k0 + 0][row] = b0.x; Bs[k0 + 1][row] = b0.y;
            Bs[k0 + 2][row] = b0.z; Bs[k0 + 3][row] = b0.w;
            Bs[k0 + 4][row] = b1.x; Bs[k0 + 5][row] = b1.y;
            Bs[k0 + 6][row] = b1.z; Bs[k0 + 7][row] = b1.w;
        }
        __syncthreads();
#pragma unroll
        for (int k = 0; k < 32; k++) {
            float a[8], bb[8];
#pragma unroll
            for (int i = 0; i < 8; i++) a[i]  = As[k][ty * 8 + i];
#pragma unroll
            for (int j = 0; j < 8; j++) bb[j] = Bs[k][tx * 8 + j];
#pragma unroll
            for (int i = 0; i < 8; i++)
#pragma unroll
                for (int j = 0; j < 8; j++)
                    acc[i][j] = fmaf(a[i], bb[j], acc[i][j]);
        }
        __syncthreads();
    }

    float* sp = g_s + (size_t)b * N_ * N_;
#pragma unroll
    for (int i = 0; i < 8; i++) {
        int n = nBase + ty * 8 + i;
#pragma unroll
        for (int j4 = 0; j4 < 2; j4++) {
            float4 v = make_float4(acc[i][j4 * 4 + 0], acc[i][j4 * 4 + 1],
                                   acc[i][j4 * 4 + 2], acc[i][j4 * 4 + 3]);
            *reinterpret_cast<float4*>(&sp[(size_t)n * N_ + mBase + tx * 8 + j4 * 4]) = v;
        }
    }
}

// ---------------------------------------------------------------------------
// Kernel 3: row softmax over g_s (32768 rows of 1024)
// ---------------------------------------------------------------------------
__global__ __launch_bounds__(256) void k_softmax()
{
    const int row = blockIdx.x;
    float* sp = g_s + (size_t)row * N_;
    const int tid = threadIdx.x;
    float v[4];
#pragma unroll
    for (int i = 0; i < 4; i++) v[i] = sp[tid + i * 256];

    __shared__ float red[256];
    float m = fmaxf(fmaxf(v[0], v[1]), fmaxf(v[2], v[3]));
    red[tid] = m;
    __syncthreads();
    for (int s = 128; s > 0; s >>= 1) {
        if (tid < s) red[tid] = fmaxf(red[tid], red[tid + s]);
        __syncthreads();
    }
    m = red[0];
    __syncthreads();

    float e[4], sum = 0.f;
#pragma unroll
    for (int i = 0; i < 4; i++) { e[i] = __expf(v[i] - m); sum += e[i]; }
    red[tid] = sum;
    __syncthreads();
    for (int s = 128; s > 0; s >>= 1) {
        if (tid < s) red[tid] += red[tid + s];
        __syncthreads();
    }
    float inv = 1.0f / red[0];
#pragma unroll
    for (int i = 0; i < 4; i++) sp[tid + i * 256] = e[i] * inv;
}

// ---------------------------------------------------------------------------
// Kernel 4: o[b] = beta[b] @ h_fl[b]  (M=1024, N=768, K=1024)
// Epilogue fuses hw_recover + gamma*o + x directly into d_out.
// Tiles: 128x128x16, 256 thr, 8x8 per thread.
// ---------------------------------------------------------------------------
__global__ __launch_bounds__(256) void k_o(
    const float* __restrict__ x, const float* __restrict__ gammaP,
    float* __restrict__ out)
{
    __shared__ float As[16][128];
    __shared__ float Bs[16][128];
    const int tid   = threadIdx.x;
    const int b     = blockIdx.z;
    const int cBase = blockIdx.x * 128;   // 0..5 (N=768)
    const int nBase = blockIdx.y * 128;
    const int ty = tid >> 4, tx = tid & 15;
    const int ar  = tid >> 1;
    const int ak0 = (tid & 1) * 8;

    const float* Ab = g_s + (size_t)b * N_ * N_;
    const float* Bb = g_h + (size_t)b * N_ * HC_;

    float acc[8][8];
#pragma unroll
    for (int i = 0; i < 8; i++)
#pragma unroll
        for (int j = 0; j < 8; j++) acc[i][j] = 0.f;

    for (int kT = 0; kT < N_; kT += 16) {
        const float* ap = Ab + (size_t)(nBase + ar) * N_ + kT + ak0;
        float4 a0 = *reinterpret_cast<const float4*>(ap);
        float4 a1 = *reinterpret_cast<const float4*>(ap + 4);
        As[ak0 + 0][ar] = a0.x; As[ak0 + 1][ar] = a0.y;
        As[ak0 + 2][ar] = a0.z; As[ak0 + 3][ar] = a0.w;
        As[ak0 + 4][ar] = a1.x; As[ak0 + 5][ar] = a1.y;
        As[ak0 + 6][ar] = a1.z; As[ak0 + 7][ar] = a1.w;
#pragma unroll
        for (int i = 0; i < 2; i++) {
            int l  = tid + i * 256;       // float4 index (512 total)
            int k  = l >> 5;
            int c4 = (l & 31) * 4;
            *reinterpret_cast<float4*>(&Bs[k][c4]) =
                *reinterpret_cast<const float4*>(&Bb[(size_t)(kT + k) * HC_ + cBase + c4]);
        }
        __syncthreads();
#pragma unroll
        for (int k = 0; k < 16; k++) {
            float a[8], bb[8];
#pragma unroll
            for (int i = 0; i < 8; i++) a[i]  = As[k][ty * 8 + i];
#pragma unroll
            for (int j = 0; j < 8; j++) bb[j] = Bs[k][tx * 8 + j];
#pragma unroll
            for (int i = 0; i < 8; i++)
#pragma unroll
                for (int j = 0; j < 8; j++)
                    acc[i][j] = fmaf(a[i], bb[j], acc[i][j]);
        }
        __syncthreads();
    }

    const float gamma = __ldg(gammaP);
    const int sg = cBase >> 8;            // split group of this 128-col tile
#pragma unroll
    for (int i = 0; i < 8; i++) {
        int n  = nBase + ty * 8 + i;
        int hr = n >> 8;                  // n / W_
        int w  = n & 255;
        int h  = sg * HS_ + hr;
#pragma unroll
        for (int j4 = 0; j4 < 2; j4++) {
            int c  = cBase + tx * 8 + j4 * 4;
            int ch = c - sg * 256;
            size_t idx = (((size_t)b * H_ + h) * W_ + w) * C_ + ch;
            float4 xv = *reinterpret_cast<const float4*>(&x[idx]);
            float4 o;
            o.x = fmaf(gamma, acc[i][j4 * 4 + 0], xv.x);
            o.y = fmaf(gamma, acc[i][j4 * 4 + 1], xv.y);
            o.z = fmaf(gamma, acc[i][j4 * 4 + 2], xv.z);
            o.w = fmaf(gamma, acc[i][j4 * 4 + 3], xv.w);
            *reinterpret_cast<float4*>(&out[idx]) = o;
        }
    }
}

// ---------------------------------------------------------------------------
extern "C" void kernel_launch(void* const* d_in, const int* in_sizes, int n_in,
                              void* d_out, int out_size)
{
    const float* x     = (const float*)d_in[0];
    const float* Wf    = (const float*)d_in[1];
    const float* Wg    = (const float*)d_in[2];
    const float* Wh    = (const float*)d_in[3];
    const float* gamma = (const float*)d_in[4];
    float* out = (float*)d_out;

    k_proj   <<<dim3(5, P_ / 128), 256>>>(x, Wf, Wg, Wh);
    k_score  <<<dim3(N_ / 128, N_ / 128, B_), 256>>>();
    k_softmax<<<dim3(B_ * N_), 256>>>();
    k_o      <<<dim3(HC_ / 128, N_ / 128, B_), 256>>>(x, gamma, out);
}

// round 3
// speedup vs baseline: 2.0933x; 2.0933x over previous
#include <cuda_runtime.h>
#include <cuda_bf16.h>
#include <cstdint>

// Problem constants
constexpr int B_  = 32;
constexpr int H_  = 12;
constexpr int W_  = 256;
constexpr int C_  = 256;
constexpr int HS_ = 4;            // H / SPLIT
constexpr int N_  = HS_ * W_;     // 1024 flattened spatial
constexpr int FC_ = 96;           // SPLIT * Cf
constexpr int HC_ = 768;          // SPLIT * C
constexpr int P_  = B_ * H_ * W_; // 98304 pixels

// Scratch (device globals; no allocation in kernel_launch)
__device__ float g_f[(size_t)B_ * N_ * FC_];            // 12.6 MB
__device__ float g_g[(size_t)B_ * N_ * FC_];            // 12.6 MB
__device__ __nv_bfloat16 g_hb[(size_t)B_ * N_ * HC_];   // 50 MB  [b][n][c] bf16
__device__ float g_s[(size_t)B_ * N_ * N_];             // 134 MB
__device__ __nv_bfloat16 g_beta[(size_t)B_ * N_ * N_];  // 64 MB  [b][n][m]
__device__ __nv_bfloat16 g_hT[(size_t)B_ * HC_ * N_];   // 48 MB  [b][c][n]

// ============================ PTX helpers ==================================
__device__ __forceinline__ uint32_t smem_u32(const void* p) {
    uint32_t a;
    asm("{ .reg .u64 t; cvta.to.shared.u64 t, %1; cvt.u32.u64 %0, t; }"
        : "=r"(a) : "l"(p));
    return a;
}
#define CP16(s, g) \
    asm volatile("cp.async.cg.shared.global [%0], [%1], 16;" \
        :: "r"(s), "l"(g) : "memory")
#define CPCOMMIT() asm volatile("cp.async.commit_group;" ::: "memory")
#define CPWAIT(n)  asm volatile("cp.async.wait_group %0;" :: "n"(n) : "memory")

__device__ __forceinline__ void ldsm_x4(uint32_t& r0, uint32_t& r1,
                                        uint32_t& r2, uint32_t& r3, uint32_t addr) {
    asm volatile("ldmatrix.sync.aligned.m8n8.x4.shared.b16 {%0,%1,%2,%3}, [%4];"
        : "=r"(r0), "=r"(r1), "=r"(r2), "=r"(r3) : "r"(addr));
}
__device__ __forceinline__ void mma_bf16(float* c, const uint32_t* a, const uint32_t* b) {
    asm volatile("mma.sync.aligned.m16n8k16.row.col.f32.bf16.bf16.f32 "
        "{%0,%1,%2,%3}, {%4,%5,%6,%7}, {%8,%9}, {%0,%1,%2,%3};"
        : "+f"(c[0]), "+f"(c[1]), "+f"(c[2]), "+f"(c[3])
        : "r"(a[0]), "r"(a[1]), "r"(a[2]), "r"(a[3]), "r"(b[0]), "r"(b[1]));
}
// smem tile: 64B rows (32 bf16), 4x16B chunks/row, XOR swizzle for ldmatrix
__device__ __forceinline__ uint32_t swz(int r, int c) {
    return (uint32_t)(r * 64 + ((c ^ ((r >> 1) & 3)) << 4));
}

// ---------------------------------------------------------------------------
// Kernel 1: projections. C_all[P,320] = X[P,256] @ [Wh(256)|Wf(32)|Wg(32)]
// h goes out in bf16 (only consumed via bf16 hT); f,g stay fp32 (logits path).
// ---------------------------------------------------------------------------
__global__ __launch_bounds__(256) void k_proj(
    const float* __restrict__ x, const float* __restrict__ Wf,
    const float* __restrict__ Wg, const float* __restrict__ Wh)
{
    __shared__ float As[16][128];
    __shared__ float Bs[16][64];
    const int tid   = threadIdx.x;
    const int cBase = blockIdx.x * 64;
    const int pBase = blockIdx.y * 128;
    const int ty = tid >> 4, tx = tid & 15;
    const int ar  = tid >> 1;
    const int ak0 = (tid & 1) * 8;

    float acc[8][4];
#pragma unroll
    for (int i = 0; i < 8; i++)
#pragma unroll
        for (int j = 0; j < 4; j++) acc[i][j] = 0.f;

    for (int kT = 0; kT < 256; kT += 16) {
        const float* ap = x + (size_t)(pBase + ar) * 256 + (kT + ak0);
        float4 a0 = *reinterpret_cast<const float4*>(ap);
        float4 a1 = *reinterpret_cast<const float4*>(ap + 4);
        As[ak0 + 0][ar] = a0.x; As[ak0 + 1][ar] = a0.y;
        As[ak0 + 2][ar] = a0.z; As[ak0 + 3][ar] = a0.w;
        As[ak0 + 4][ar] = a1.x; As[ak0 + 5][ar] = a1.y;
        As[ak0 + 6][ar] = a1.z; As[ak0 + 7][ar] = a1.w;
#pragma unroll
        for (int i = 0; i < 4; i++) {
            int l  = tid + i * 256;
            int bk = l >> 6, jl = l & 63;
            int j  = cBase + jl;
            float v;
            if (j < 256)      v = Wh[(kT + bk) * 256 + j];
            else if (j < 288) v = Wf[(kT + bk) * 32 + (j - 256)];
            else              v = Wg[(kT + bk) * 32 + (j - 288)];
            Bs[bk][jl] = v;
        }
        __syncthreads();
#pragma unroll
        for (int k = 0; k < 16; k++) {
            float a[8], b[4];
#pragma unroll
            for (int i = 0; i < 8; i++) a[i] = As[k][ty * 8 + i];
#pragma unroll
            for (int j = 0; j < 4; j++) b[j] = Bs[k][tx * 4 + j];
#pragma unroll
            for (int i = 0; i < 8; i++)
#pragma unroll
                for (int j = 0; j < 4; j++)
                    acc[i][j] = fmaf(a[i], b[j], acc[i][j]);
        }
        __syncthreads();
    }

#pragma unroll
    for (int i = 0; i < 8; i++) {
        int p   = pBase + ty * 8 + i;
        int b   = p / (H_ * W_);
        int rem = p - b * (H_ * W_);
        int h   = rem >> 8;
        int w   = rem & 255;
        int sg  = h >> 2;
        int hr  = h & 3;
        int n   = hr * W_ + w;
#pragma unroll
        for (int jj = 0; jj < 4; jj++) {
            int   j = cBase + tx * 4 + jj;
            float v = acc[i][jj];
            if (j < 256)
                g_hb[((size_t)b * N_ + n) * HC_ + sg * 256 + j] = __float2bfloat16(v);
            else if (j < 288)
                g_f[((size_t)b * N_ + n) * FC_ + sg * 32 + (j - 256)] = v;
            else
                g_g[((size_t)b * N_ + n) * FC_ + sg * 32 + (j - 288)] = v;
        }
    }
}

// ---------------------------------------------------------------------------
// Kernel 1b: transpose h: g_hb [b][n][c] bf16 -> g_hT [b][c][n] bf16
// ---------------------------------------------------------------------------
__global__ __launch_bounds__(256) void k_transpose_h()
{
    __shared__ __nv_bfloat16 t[32][33];
    const int b  = blockIdx.z;
    const int nB = blockIdx.x * 32;
    const int cB = blockIdx.y * 32;
    const int tid = threadIdx.x;
    const int cl = tid & 31, rl = tid >> 5;

    const __nv_bfloat16* src = g_hb + ((size_t)b * N_ + nB) * HC_ + cB;
#pragma unroll
    for (int i = 0; i < 4; i++) {
        int nl = rl + i * 8;
        t[nl][cl] = src[(size_t)nl * HC_ + cl];
    }
    __syncthreads();
    __nv_bfloat16* dst = g_hT + ((size_t)b * HC_ + cB) * N_ + nB;
#pragma unroll
    for (int i = 0; i < 4; i++) {
        int c2 = rl + i * 8;
        dst[(size_t)c2 * N_ + cl] = t[cl][c2];
    }
}

// ---------------------------------------------------------------------------
// Kernel 2: s[b] = g_fl[b] @ f_fl[b]^T   (fp32 FMA, logits precision-critical)
// ---------------------------------------------------------------------------
__global__ __launch_bounds__(256) void k_score()
{
    __shared__ float As[32][128];
    __shared__ float Bs[32][128];
    const int tid   = threadIdx.x;
    const int b     = blockIdx.z;
    const int mBase = blockIdx.x * 128;
    const int nBase = blockIdx.y * 128;
    const int ty = tid >> 4, tx = tid & 15;

    const float* Ab = g_g + (size_t)b * N_ * FC_;
    const float* Bb = g_f + (size_t)b * N_ * FC_;

    float acc[8][8];
#pragma unroll
    for (int i = 0; i < 8; i++)
#pragma unroll
        for (int j = 0; j < 8; j++) acc[i][j] = 0.f;

    for (int kT = 0; kT < FC_; kT += 32) {
#pragma unroll
        for (int sgi = 0; sgi < 2; sgi++) {
            int sid = tid * 2 + sgi;
            int row = sid >> 2;
            int k0  = (sid & 3) * 8;
            const float* ap = Ab + (size_t)(nBase + row) * FC_ + kT + k0;
            float4 a0 = *reinterpret_cast<const float4*>(ap);
            float4 a1 = *reinterpret_cast<const float4*>(ap + 4);
            As[k0 + 0][row] = a0.x; As[k0 + 1][row] = a0.y;
            As[k0 + 2][row] = a0.z; As[k0 + 3][row] = a0.w;
            As[k0 + 4][row] = a1.x; As[k0 + 5][row] = a1.y;
            As[k0 + 6][row] = a1.z; As[k0 + 7][row] = a1.w;
            const float* bp = Bb + (size_t)(mBase + row) * FC_ + kT + k0;
            float4 b0 = *reinterpret_cast<const float4*>(bp);
            float4 b1 = *reinterpret_cast<const float4*>(bp + 4);
            Bs[k0 + 0][row] = b0.x; Bs[k0 + 1][row] = b0.y;
            Bs[k0 + 2][row] = b0.z; Bs[k0 + 3][row] = b0.w;
            Bs[k0 + 4][row] = b1.x; Bs[k0 + 5][row] = b1.y;
            Bs[k0 + 6][row] = b1.z; Bs[k0 + 7][row] = b1.w;
        }
        __syncthreads();
#pragma unroll
        for (int k = 0; k < 32; k++) {
            float a[8], bb[8];
#pragma unroll
            for (int i = 0; i < 8; i++) a[i]  = As[k][ty * 8 + i];
#pragma unroll
            for (int j = 0; j < 8; j++) bb[j] = Bs[k][tx * 8 + j];
#pragma unroll
            for (int i = 0; i < 8; i++)
#pragma unroll
                for (int j = 0; j < 8; j++)
                    acc[i][j] = fmaf(a[i], bb[j], acc[i][j]);
        }
        __syncthreads();
    }

    float* sp = g_s + (size_t)b * N_ * N_;
#pragma unroll
    for (int i = 0; i < 8; i++) {
        int n = nBase + ty * 8 + i;
#pragma unroll
        for (int j4 = 0; j4 < 2; j4++) {
            float4 v = make_float4(acc[i][j4 * 4 + 0], acc[i][j4 * 4 + 1],
                                   acc[i][j4 * 4 + 2], acc[i][j4 * 4 + 3]);
            *reinterpret_cast<float4*>(&sp[(size_t)n * N_ + mBase + tx * 8 + j4 * 4]) = v;
        }
    }
}

// ---------------------------------------------------------------------------
// Kernel 3: row softmax over g_s; writes bf16 beta
// ---------------------------------------------------------------------------
__global__ __launch_bounds__(256) void k_softmax()
{
    const size_t row = blockIdx.x;
    const float* sp = g_s + row * N_;
    __nv_bfloat16* bp = g_beta + row * N_;
    const int tid = threadIdx.x;
    float v[4];
#pragma unroll
    for (int i = 0; i < 4; i++) v[i] = sp[tid + i * 256];

    __shared__ float red[256];
    float m = fmaxf(fmaxf(v[0], v[1]), fmaxf(v[2], v[3]));
    red[tid] = m;
    __syncthreads();
    for (int s = 128; s > 0; s >>= 1) {
        if (tid < s) red[tid] = fmaxf(red[tid], red[tid + s]);
        __syncthreads();
    }
    m = red[0];
    __syncthreads();

    float e[4], sum = 0.f;
#pragma unroll
    for (int i = 0; i < 4; i++) { e[i] = __expf(v[i] - m); sum += e[i]; }
    red[tid] = sum;
    __syncthreads();
    for (int s = 128; s > 0; s >>= 1) {
        if (tid < s) red[tid] += red[tid + s];
        __syncthreads();
    }
    float inv = 1.0f / red[0];
#pragma unroll
    for (int i = 0; i < 4; i++)
        bp[tid + i * 256] = __float2bfloat16(e[i] * inv);
}

// ---------------------------------------------------------------------------
// Kernel 4: bf16 HMMA GEMM  o[b] = beta[b] @ h_fl[b]  (M=1024, N=768, K=1024)
// CTA tile 128x128x32, 8 warps (4m x 2n), warp tile 32x64 via m16n8k16.
// 3-stage cp.async pipeline, ldmatrix from swizzled smem.
// Epilogue fuses hw_recover + gamma*o + x.
// ---------------------------------------------------------------------------
constexpr int BK_    = 32;
constexpr int NK_    = N_ / BK_;   // 32 k-chunks
constexpr int STAGE_ = 16384;      // 8KB A + 8KB B per stage
constexpr int STGS_  = 3;

__global__ __launch_bounds__(256) void k_o_mma(
    const float* __restrict__ x, const float* __restrict__ gammaP,
    float* __restrict__ out)
{
    __shared__ __align__(1024) char smem[STGS_ * STAGE_];
    const uint32_t sbase = smem_u32(smem);

    const int tid  = threadIdx.x;
    const int wid  = tid >> 5;
    const int lane = tid & 31;
    const int wm   = wid & 3;      // 4 m-warps * 32 rows
    const int wn   = wid >> 2;     // 2 n-warps * 64 cols
    const int b     = blockIdx.z;
    const int mBase = blockIdx.y * 128;
    const int cBase = blockIdx.x * 128;

    const __nv_bfloat16* gA = g_beta + ((size_t)b * N_ + mBase) * N_;  // [128][1024]
    const __nv_bfloat16* gB = g_hT  + ((size_t)b * HC_ + cBase) * N_;  // [128][1024]

    // per-thread load slots: 2 x 16B for A, 2 x 16B for B
    const int lr = tid >> 2;            // rows 0..63 (+64 for i=1)
    const int lc = tid & 3;             // 16B chunk within 64B row

    auto issue = [&](int slot, int kc) {
        const uint32_t aS = sbase + slot * STAGE_;
        const uint32_t bS = aS + 8192;
        const int kOff = kc * BK_ + lc * 8;   // bf16 offset
#pragma unroll
        for (int i = 0; i < 2; i++) {
            int r = lr + i * 64;
            CP16(aS + swz(r, lc), gA + (size_t)r * N_ + kOff);
        }
#pragma unroll
        for (int i = 0; i < 2; i++) {
            int r = lr + i * 64;
            CP16(bS + swz(r, lc), gB + (size_t)r * N_ + kOff);
        }
    };

    float acc[2][8][4];
#pragma unroll
    for (int mt = 0; mt < 2; mt++)
#pragma unroll
        for (int nt = 0; nt < 8; nt++)
#pragma unroll
            for (int j = 0; j < 4; j++) acc[mt][nt][j] = 0.f;

    issue(0, 0); CPCOMMIT();
    issue(1, 1); CPCOMMIT();

    for (int kc = 0; kc < NK_; kc++) {
        if (kc + 2 < NK_) {
            issue((kc + 2) % STGS_, kc + 2); CPCOMMIT();
            CPWAIT(2);
        } else {
            CPWAIT(0);
        }
        __syncthreads();

        const uint32_t aS = sbase + (kc % STGS_) * STAGE_;
        const uint32_t bS = aS + 8192;
#pragma unroll
        for (int ks = 0; ks < 2; ks++) {
            uint32_t afr[2][4];
#pragma unroll
            for (int mt = 0; mt < 2; mt++) {
                int row = wm * 32 + mt * 16 + ((lane >> 3) & 1) * 8 + (lane & 7);
                int ch  = ks * 2 + (lane >> 4);
                ldsm_x4(afr[mt][0], afr[mt][1], afr[mt][2], afr[mt][3],
                        aS + swz(row, ch));
            }
            uint32_t bfr[8][2];
#pragma unroll
            for (int p = 0; p < 4; p++) {
                int row = wn * 64 + p * 16 + (lane >> 4) * 8 + (lane & 7);
                int ch  = ks * 2 + ((lane >> 3) & 1);
                uint32_t r0, r1, r2, r3;
                ldsm_x4(r0, r1, r2, r3, bS + swz(row, ch));
                bfr[2 * p][0] = r0; bfr[2 * p][1] = r1;
                bfr[2 * p + 1][0] = r2; bfr[2 * p + 1][1] = r3;
            }
#pragma unroll
            for (int mt = 0; mt < 2; mt++)
#pragma unroll
                for (int nt = 0; nt < 8; nt++)
                    mma_bf16(acc[mt][nt], afr[mt], bfr[nt]);
        }
        __syncthreads();
    }

    // Epilogue: fuse hw_recover + gamma*o + x
    const float gamma = __ldg(gammaP);
    const int gr = lane >> 2;
    const int qc = (lane & 3) * 2;
#pragma unroll
    for (int mt = 0; mt < 2; mt++) {
#pragma unroll
        for (int rr = 0; rr < 2; rr++) {
            int m    = mBase + wm * 32 + mt * 16 + rr * 8 + gr;
            int hr   = m >> 8;
            int wpix = m & 255;
#pragma unroll
            for (int nt = 0; nt < 8; nt++) {
                int cg = cBase + wn * 64 + nt * 8 + qc;
                int sg = cg >> 8;
                int ch = cg & 255;
                int hh = sg * HS_ + hr;
                size_t idx = (((size_t)b * H_ + hh) * W_ + wpix) * C_ + ch;
                float2 xv = *reinterpret_cast<const float2*>(x + idx);
                float2 o;
                o.x = fmaf(gamma, acc[mt][nt][rr * 2 + 0], xv.x);
                o.y = fmaf(gamma, acc[mt][nt][rr * 2 + 1], xv.y);
                *reinterpret_cast<float2*>(out + idx) = o;
            }
        }
    }
}

// ---------------------------------------------------------------------------
extern "C" void kernel_launch(void* const* d_in, const int* in_sizes, int n_in,
                              void* d_out, int out_size)
{
    const float* x     = (const float*)d_in[0];
    const float* Wf    = (const float*)d_in[1];
    const float* Wg    = (const float*)d_in[2];
    const float* Wh    = (const float*)d_in[3];
    const float* gamma = (const float*)d_in[4];
    float* out = (float*)d_out;

    k_proj       <<<dim3(5, P_ / 128), 256>>>(x, Wf, Wg, Wh);
    k_transpose_h<<<dim3(N_ / 32, HC_ / 32, B_), 256>>>();
    k_score      <<<dim3(N_ / 128, N_ / 128, B_), 256>>>();
    k_softmax    <<<dim3(B_ * N_), 256>>>();
    k_o_mma      <<<dim3(HC_ / 128, N_ / 128, B_), 256>>>(x, gamma, out);
}

// round 4
// speedup vs baseline: 4.0692x; 1.9439x over previous
#include <cuda_runtime.h>
#include <cuda_bf16.h>
#include <cstdint>

// Problem constants
constexpr int B_  = 32;
constexpr int H_  = 12;
constexpr int W_  = 256;
constexpr int C_  = 256;
constexpr int HS_ = 4;            // H / SPLIT
constexpr int N_  = HS_ * W_;     // 1024 flattened spatial
constexpr int FC_ = 96;           // SPLIT * Cf
constexpr int HC_ = 768;          // SPLIT * C
constexpr int P_  = B_ * H_ * W_; // 98304 pixels

// Scratch (device globals)
__device__ __nv_bfloat16 g_xhi[(size_t)P_ * C_];        // 50 MB
__device__ __nv_bfloat16 g_xlo[(size_t)P_ * C_];        // 50 MB
__device__ __nv_bfloat16 g_Wthi[320 * 256];             // [j][k] transposed concat
__device__ __nv_bfloat16 g_Wtlo[320 * 256];
__device__ __nv_bfloat16 g_fhi[(size_t)B_ * N_ * FC_];  // 6.3 MB each
__device__ __nv_bfloat16 g_flo[(size_t)B_ * N_ * FC_];
__device__ __nv_bfloat16 g_ghi[(size_t)B_ * N_ * FC_];
__device__ __nv_bfloat16 g_glo[(size_t)B_ * N_ * FC_];
__device__ __nv_bfloat16 g_hb[(size_t)B_ * N_ * HC_];   // 50 MB  [b][n][c]
__device__ float g_s[(size_t)B_ * N_ * N_];             // 134 MB
__device__ __nv_bfloat16 g_beta[(size_t)B_ * N_ * N_];  // 64 MB  [b][n][m]
__device__ __nv_bfloat16 g_hT[(size_t)B_ * HC_ * N_];   // 48 MB  [b][c][n]

// ============================ PTX helpers ==================================
__device__ __forceinline__ uint32_t smem_u32(const void* p) {
    uint32_t a;
    asm("{ .reg .u64 t; cvta.to.shared.u64 t, %1; cvt.u32.u64 %0, t; }"
        : "=r"(a) : "l"(p));
    return a;
}
#define CP16(s, g) \
    asm volatile("cp.async.cg.shared.global [%0], [%1], 16;" \
        :: "r"(s), "l"(g) : "memory")
#define CPCOMMIT() asm volatile("cp.async.commit_group;" ::: "memory")
#define CPWAIT(n)  asm volatile("cp.async.wait_group %0;" :: "n"(n) : "memory")

__device__ __forceinline__ void ldsm_x4(uint32_t& r0, uint32_t& r1,
                                        uint32_t& r2, uint32_t& r3, uint32_t addr) {
    asm volatile("ldmatrix.sync.aligned.m8n8.x4.shared.b16 {%0,%1,%2,%3}, [%4];"
        : "=r"(r0), "=r"(r1), "=r"(r2), "=r"(r3) : "r"(addr));
}
__device__ __forceinline__ void mma_bf16(float* c, const uint32_t* a, const uint32_t* b) {
    asm volatile("mma.sync.aligned.m16n8k16.row.col.f32.bf16.bf16.f32 "
        "{%0,%1,%2,%3}, {%4,%5,%6,%7}, {%8,%9}, {%0,%1,%2,%3};"
        : "+f"(c[0]), "+f"(c[1]), "+f"(c[2]), "+f"(c[3])
        : "r"(a[0]), "r"(a[1]), "r"(a[2]), "r"(a[3]), "r"(b[0]), "r"(b[1]));
}
// smem tile: 64B rows (32 bf16), 4x16B chunks/row, XOR swizzle for ldmatrix
__device__ __forceinline__ uint32_t swz(int r, int c) {
    return (uint32_t)(r * 64 + ((c ^ ((r >> 1) & 3)) << 4));
}
__device__ __forceinline__ void split2(float v, __nv_bfloat16& hi, __nv_bfloat16& lo) {
    hi = __float2bfloat16(v);
    lo = __float2bfloat16(v - __bfloat162float(hi));
}

// ---------------------------------------------------------------------------
// Kernel 0a: split x into bf16 hi/lo
// ---------------------------------------------------------------------------
__global__ __launch_bounds__(256) void k_split_x(const float* __restrict__ x)
{
    size_t gid = (size_t)blockIdx.x * 256 + threadIdx.x;   // float4 index
    float4 v = reinterpret_cast<const float4*>(x)[gid];
    __nv_bfloat16 h0, h1, h2, h3, l0, l1, l2, l3;
    split2(v.x, h0, l0); split2(v.y, h1, l1);
    split2(v.z, h2, l2); split2(v.w, h3, l3);
    uint2 hu, lu;
    reinterpret_cast<__nv_bfloat162*>(&hu)[0] = __nv_bfloat162(h0, h1);
    reinterpret_cast<__nv_bfloat162*>(&hu)[1] = __nv_bfloat162(h2, h3);
    reinterpret_cast<__nv_bfloat162*>(&lu)[0] = __nv_bfloat162(l0, l1);
    reinterpret_cast<__nv_bfloat162*>(&lu)[1] = __nv_bfloat162(l2, l3);
    reinterpret_cast<uint2*>(g_xhi)[gid] = hu;
    reinterpret_cast<uint2*>(g_xlo)[gid] = lu;
}

// ---------------------------------------------------------------------------
// Kernel 0b: build transposed split concat weight Wt[j][k], j in [0,320)
// ---------------------------------------------------------------------------
__global__ __launch_bounds__(256) void k_split_w(
    const float* __restrict__ Wf, const float* __restrict__ Wg,
    const float* __restrict__ Wh)
{
    const int j = blockIdx.x;
    const int k = threadIdx.x;
    float v;
    if (j < 256)      v = Wh[k * 256 + j];
    else if (j < 288) v = Wf[k * 32 + (j - 256)];
    else              v = Wg[k * 32 + (j - 288)];
    __nv_bfloat16 hi, lo;
    split2(v, hi, lo);
    g_Wthi[j * 256 + k] = hi;
    g_Wtlo[j * 256 + k] = lo;
}

// ---------------------------------------------------------------------------
// Kernel 1: projections via 3-pass bf16 HMMA.
// C[P,320] = X[P,256] @ Wt^T. Tile 128x64x32, 8 warps (4m x 2n).
// Epilogue scatters h (bf16) and f/g (hi/lo bf16) into flattened layouts.
// ---------------------------------------------------------------------------
constexpr int PJ_STAGE = 24576;   // Ah 8K + Al 8K + Bh 4K + Bl 4K
constexpr int PJ_STGS  = 3;

__global__ __launch_bounds__(256) void k_proj_mma()
{
    extern __shared__ char smem[];
    const uint32_t sbase = smem_u32(smem);
    const int tid  = threadIdx.x;
    const int wid  = tid >> 5;
    const int lane = tid & 31;
    const int wm   = wid & 3;
    const int wn   = wid >> 2;
    const int cBase = blockIdx.x * 64;     // 5 blocks
    const int pBase = blockIdx.y * 128;

    const __nv_bfloat16* gAh = g_xhi + (size_t)pBase * 256;
    const __nv_bfloat16* gAl = g_xlo + (size_t)pBase * 256;
    const __nv_bfloat16* gBh = g_Wthi + (size_t)cBase * 256;
    const __nv_bfloat16* gBl = g_Wtlo + (size_t)cBase * 256;

    // A: 512 chunks (2/thread). B: 256 chunks (1/thread).
    const int arow = tid >> 2, ac = tid & 3;
    auto issue = [&](int slot, int kc) {
        const uint32_t st = sbase + slot * PJ_STAGE;
        const int kOff = kc * 32 + ac * 8;
#pragma unroll
        for (int i = 0; i < 2; i++) {
            int idx = i * 256 + tid;
            int r = idx >> 2, c = idx & 3;
            int ko = kc * 32 + c * 8;
            CP16(st + swz(r, c), gAh + (size_t)r * 256 + ko);
            CP16(st + 8192 + swz(r, c), gAl + (size_t)r * 256 + ko);
        }
        if (arow < 64) {
            CP16(st + 16384 + swz(arow, ac), gBh + (size_t)arow * 256 + kOff);
            CP16(st + 20480 + swz(arow, ac), gBl + (size_t)arow * 256 + kOff);
        }
    };

    float acc[2][4][4];
#pragma unroll
    for (int mt = 0; mt < 2; mt++)
#pragma unroll
        for (int nt = 0; nt < 4; nt++)
#pragma unroll
            for (int j = 0; j < 4; j++) acc[mt][nt][j] = 0.f;

    issue(0, 0); CPCOMMIT();
    issue(1, 1); CPCOMMIT();

    for (int kc = 0; kc < 8; kc++) {
        if (kc + 2 < 8) {
            issue((kc + 2) % PJ_STGS, kc + 2); CPCOMMIT();
            CPWAIT(2);
        } else {
            CPWAIT(0);
        }
        __syncthreads();
        const uint32_t st = sbase + (kc % PJ_STGS) * PJ_STAGE;
#pragma unroll
        for (int ks = 0; ks < 2; ks++) {
            uint32_t ah[2][4], al[2][4];
#pragma unroll
            for (int mt = 0; mt < 2; mt++) {
                int row = wm * 32 + mt * 16 + ((lane >> 3) & 1) * 8 + (lane & 7);
                int ch  = ks * 2 + (lane >> 4);
                ldsm_x4(ah[mt][0], ah[mt][1], ah[mt][2], ah[mt][3], st + swz(row, ch));
                ldsm_x4(al[mt][0], al[mt][1], al[mt][2], al[mt][3], st + 8192 + swz(row, ch));
            }
            uint32_t bh[4][2], bl[4][2];
#pragma unroll
            for (int p = 0; p < 2; p++) {
                int row = wn * 32 + p * 16 + (lane >> 4) * 8 + (lane & 7);
                int ch  = ks * 2 + ((lane >> 3) & 1);
                uint32_t r0, r1, r2, r3;
                ldsm_x4(r0, r1, r2, r3, st + 16384 + swz(row, ch));
                bh[2 * p][0] = r0; bh[2 * p][1] = r1;
                bh[2 * p + 1][0] = r2; bh[2 * p + 1][1] = r3;
                ldsm_x4(r0, r1, r2, r3, st + 20480 + swz(row, ch));
                bl[2 * p][0] = r0; bl[2 * p][1] = r1;
                bl[2 * p + 1][0] = r2; bl[2 * p + 1][1] = r3;
            }
#pragma unroll
            for (int mt = 0; mt < 2; mt++)
#pragma unroll
                for (int nt = 0; nt < 4; nt++) {
                    mma_bf16(acc[mt][nt], ah[mt], bh[nt]);
                    mma_bf16(acc[mt][nt], ah[mt], bl[nt]);
                    mma_bf16(acc[mt][nt], al[mt], bh[nt]);
                }
        }
        __syncthreads();
    }

    // Epilogue: scatter
    const int gr = lane >> 2;
    const int qc = (lane & 3) * 2;
#pragma unroll
    for (int mt = 0; mt < 2; mt++) {
#pragma unroll
        for (int rr = 0; rr < 2; rr++) {
            int p   = pBase + wm * 32 + mt * 16 + rr * 8 + gr;
            int b   = p / (H_ * W_);
            int rem = p - b * (H_ * W_);
            int h   = rem >> 8;
            int w   = rem & 255;
            int sg  = h >> 2;
            int hr  = h & 3;
            int n   = hr * W_ + w;
#pragma unroll
            for (int nt = 0; nt < 4; nt++) {
                int j = cBase + wn * 32 + nt * 8 + qc;
                float v0 = acc[mt][nt][rr * 2 + 0];
                float v1 = acc[mt][nt][rr * 2 + 1];
                if (j < 256) {
                    __nv_bfloat162 hv(__float2bfloat16(v0), __float2bfloat16(v1));
                    *reinterpret_cast<__nv_bfloat162*>(
                        &g_hb[((size_t)b * N_ + n) * HC_ + sg * 256 + j]) = hv;
                } else {
                    __nv_bfloat16 h0, h1, l0, l1;
                    split2(v0, h0, l0); split2(v1, h1, l1);
                    __nv_bfloat162 hv(h0, h1), lv(l0, l1);
                    if (j < 288) {
                        size_t idx = ((size_t)b * N_ + n) * FC_ + sg * 32 + (j - 256);
                        *reinterpret_cast<__nv_bfloat162*>(&g_fhi[idx]) = hv;
                        *reinterpret_cast<__nv_bfloat162*>(&g_flo[idx]) = lv;
                    } else {
                        size_t idx = ((size_t)b * N_ + n) * FC_ + sg * 32 + (j - 288);
                        *reinterpret_cast<__nv_bfloat162*>(&g_ghi[idx]) = hv;
                        *reinterpret_cast<__nv_bfloat162*>(&g_glo[idx]) = lv;
                    }
                }
            }
        }
    }
}

// ---------------------------------------------------------------------------
// Kernel 1b: transpose h: g_hb [b][n][c] bf16 -> g_hT [b][c][n] bf16
// ---------------------------------------------------------------------------
__global__ __launch_bounds__(256) void k_transpose_h()
{
    __shared__ __nv_bfloat16 t[32][33];
    const int b  = blockIdx.z;
    const int nB = blockIdx.x * 32;
    const int cB = blockIdx.y * 32;
    const int tid = threadIdx.x;
    const int cl = tid & 31, rl = tid >> 5;

    const __nv_bfloat16* src = g_hb + ((size_t)b * N_ + nB) * HC_ + cB;
#pragma unroll
    for (int i = 0; i < 4; i++) {
        int nl = rl + i * 8;
        t[nl][cl] = src[(size_t)nl * HC_ + cl];
    }
    __syncthreads();
    __nv_bfloat16* dst = g_hT + ((size_t)b * HC_ + cB) * N_ + nB;
#pragma unroll
    for (int i = 0; i < 4; i++) {
        int c2 = rl + i * 8;
        dst[(size_t)c2 * N_ + cl] = t[cl][c2];
    }
}

// ---------------------------------------------------------------------------
// Kernel 2: s[b] = g_fl[b] @ f_fl[b]^T via 3-pass bf16 HMMA.
// Tile 128x128, K=96 one-shot (3 subtiles of 32). 8 warps (4m x 2n).
// ---------------------------------------------------------------------------
constexpr int SC_BUF = 24576;   // one operand buffer: 3 subtiles x 8KB

__global__ __launch_bounds__(256) void k_score_mma()
{
    extern __shared__ char smem[];
    const uint32_t sbase = smem_u32(smem);
    const int tid  = threadIdx.x;
    const int wid  = tid >> 5;
    const int lane = tid & 31;
    const int wm   = wid & 3;
    const int wn   = wid >> 2;
    const int b     = blockIdx.z;
    const int mBase = blockIdx.x * 128;   // cols of s (f index)
    const int nBase = blockIdx.y * 128;   // rows of s (g index)

    const __nv_bfloat16* srcs[4] = {
        g_ghi + ((size_t)b * N_ + nBase) * FC_,
        g_glo + ((size_t)b * N_ + nBase) * FC_,
        g_fhi + ((size_t)b * N_ + mBase) * FC_,
        g_flo + ((size_t)b * N_ + mBase) * FC_ };

    // load everything: 4 bufs x 3 subtiles x 512 chunks / 256 thr
#pragma unroll
    for (int bf = 0; bf < 4; bf++) {
        const __nv_bfloat16* src = srcs[bf];
        const uint32_t bufS = sbase + bf * SC_BUF;
#pragma unroll
        for (int t = 0; t < 3; t++)
#pragma unroll
            for (int i = 0; i < 2; i++) {
                int idx = i * 256 + tid;
                int r = idx >> 2, c = idx & 3;
                CP16(bufS + t * 8192 + swz(r, c),
                     src + (size_t)r * FC_ + t * 32 + c * 8);
            }
    }
    CPCOMMIT(); CPWAIT(0);
    __syncthreads();

    float acc[2][8][4];
#pragma unroll
    for (int mt = 0; mt < 2; mt++)
#pragma unroll
        for (int nt = 0; nt < 8; nt++)
#pragma unroll
            for (int j = 0; j < 4; j++) acc[mt][nt][j] = 0.f;

    const uint32_t AhS = sbase, AlS = sbase + SC_BUF;
    const uint32_t BhS = sbase + 2 * SC_BUF, BlS = sbase + 3 * SC_BUF;

#pragma unroll
    for (int t = 0; t < 3; t++) {
#pragma unroll
        for (int ks = 0; ks < 2; ks++) {
            uint32_t ah[2][4], al[2][4];
#pragma unroll
            for (int mt = 0; mt < 2; mt++) {
                int row = wm * 32 + mt * 16 + ((lane >> 3) & 1) * 8 + (lane & 7);
                int ch  = ks * 2 + (lane >> 4);
                ldsm_x4(ah[mt][0], ah[mt][1], ah[mt][2], ah[mt][3],
                        AhS + t * 8192 + swz(row, ch));
                ldsm_x4(al[mt][0], al[mt][1], al[mt][2], al[mt][3],
                        AlS + t * 8192 + swz(row, ch));
            }
            uint32_t bh[8][2], bl[8][2];
#pragma unroll
            for (int p = 0; p < 4; p++) {
                int row = wn * 64 + p * 16 + (lane >> 4) * 8 + (lane & 7);
                int ch  = ks * 2 + ((lane >> 3) & 1);
                uint32_t r0, r1, r2, r3;
                ldsm_x4(r0, r1, r2, r3, BhS + t * 8192 + swz(row, ch));
                bh[2 * p][0] = r0; bh[2 * p][1] = r1;
                bh[2 * p + 1][0] = r2; bh[2 * p + 1][1] = r3;
                ldsm_x4(r0, r1, r2, r3, BlS + t * 8192 + swz(row, ch));
                bl[2 * p][0] = r0; bl[2 * p][1] = r1;
                bl[2 * p + 1][0] = r2; bl[2 * p + 1][1] = r3;
            }
#pragma unroll
            for (int mt = 0; mt < 2; mt++)
#pragma unroll
                for (int nt = 0; nt < 8; nt++) {
                    mma_bf16(acc[mt][nt], ah[mt], bh[nt]);
                    mma_bf16(acc[mt][nt], ah[mt], bl[nt]);
                    mma_bf16(acc[mt][nt], al[mt], bh[nt]);
                }
        }
    }

    float* sp = g_s + (size_t)b * N_ * N_;
    const int gr = lane >> 2;
    const int qc = (lane & 3) * 2;
#pragma unroll
    for (int mt = 0; mt < 2; mt++)
#pragma unroll
        for (int rr = 0; rr < 2; rr++) {
            int n = nBase + wm * 32 + mt * 16 + rr * 8 + gr;
#pragma unroll
            for (int nt = 0; nt < 8; nt++) {
                int m = mBase + wn * 64 + nt * 8 + qc;
                float2 v = make_float2(acc[mt][nt][rr * 2], acc[mt][nt][rr * 2 + 1]);
                *reinterpret_cast<float2*>(&sp[(size_t)n * N_ + m]) = v;
            }
        }
}

// ---------------------------------------------------------------------------
// Kernel 3: row softmax (float4 + shuffle reductions); writes bf16 beta
// ---------------------------------------------------------------------------
__global__ __launch_bounds__(256) void k_softmax()
{
    const size_t row = blockIdx.x;
    const float4* sp4 = reinterpret_cast<const float4*>(g_s + row * N_);
    const int tid = threadIdx.x;
    const int lane = tid & 31, warp = tid >> 5;
    __shared__ float red[8];

    float4 v = sp4[tid];
    float m = fmaxf(fmaxf(v.x, v.y), fmaxf(v.z, v.w));
#pragma unroll
    for (int o = 16; o > 0; o >>= 1)
        m = fmaxf(m, __shfl_xor_sync(0xFFFFFFFF, m, o));
    if (lane == 0) red[warp] = m;
    __syncthreads();
    m = red[lane & 7];
#pragma unroll
    for (int o = 4; o > 0; o >>= 1)
        m = fmaxf(m, __shfl_xor_sync(0xFFFFFFFF, m, o));

    float e0 = __expf(v.x - m), e1 = __expf(v.y - m);
    float e2 = __expf(v.z - m), e3 = __expf(v.w - m);
    float s = e0 + e1 + e2 + e3;
#pragma unroll
    for (int o = 16; o > 0; o >>= 1)
        s += __shfl_xor_sync(0xFFFFFFFF, s, o);
    __syncthreads();
    if (lane == 0) red[warp] = s;
    __syncthreads();
    s = red[lane & 7];
#pragma unroll
    for (int o = 4; o > 0; o >>= 1)
        s += __shfl_xor_sync(0xFFFFFFFF, s, o);
    float inv = 1.0f / s;

    uint2 pk;
    reinterpret_cast<__nv_bfloat162*>(&pk)[0] =
        __nv_bfloat162(__float2bfloat16(e0 * inv), __float2bfloat16(e1 * inv));
    reinterpret_cast<__nv_bfloat162*>(&pk)[1] =
        __nv_bfloat162(__float2bfloat16(e2 * inv), __float2bfloat16(e3 * inv));
    reinterpret_cast<uint2*>(g_beta + row * N_)[tid] = pk;
}

// ---------------------------------------------------------------------------
// Kernel 4: bf16 HMMA GEMM  o[b] = beta[b] @ h_fl[b]  (unchanged from R3)
// ---------------------------------------------------------------------------
constexpr int BK_    = 32;
constexpr int NK_    = N_ / BK_;   // 32 k-chunks
constexpr int STAGE_ = 16384;      // 8KB A + 8KB B per stage
constexpr int STGS_  = 3;

__global__ __launch_bounds__(256) void k_o_mma(
    const float* __restrict__ x, const float* __restrict__ gammaP,
    float* __restrict__ out)
{
    __shared__ __align__(1024) char smem[STGS_ * STAGE_];
    const uint32_t sbase = smem_u32(smem);

    const int tid  = threadIdx.x;
    const int wid  = tid >> 5;
    const int lane = tid & 31;
    const int wm   = wid & 3;
    const int wn   = wid >> 2;
    const int b     = blockIdx.z;
    const int mBase = blockIdx.y * 128;
    const int cBase = blockIdx.x * 128;

    const __nv_bfloat16* gA = g_beta + ((size_t)b * N_ + mBase) * N_;
    const __nv_bfloat16* gB = g_hT  + ((size_t)b * HC_ + cBase) * N_;

    const int lr = tid >> 2;
    const int lc = tid & 3;

    auto issue = [&](int slot, int kc) {
        const uint32_t aS = sbase + slot * STAGE_;
        const uint32_t bS = aS + 8192;
        const int kOff = kc * BK_ + lc * 8;
#pragma unroll
        for (int i = 0; i < 2; i++) {
            int r = lr + i * 64;
            CP16(aS + swz(r, lc), gA + (size_t)r * N_ + kOff);
        }
#pragma unroll
        for (int i = 0; i < 2; i++) {
            int r = lr + i * 64;
            CP16(bS + swz(r, lc), gB + (size_t)r * N_ + kOff);
        }
    };

    float acc[2][8][4];
#pragma unroll
    for (int mt = 0; mt < 2; mt++)
#pragma unroll
        for (int nt = 0; nt < 8; nt++)
#pragma unroll
            for (int j = 0; j < 4; j++) acc[mt][nt][j] = 0.f;

    issue(0, 0); CPCOMMIT();
    issue(1, 1); CPCOMMIT();

    for (int kc = 0; kc < NK_; kc++) {
        if (kc + 2 < NK_) {
            issue((kc + 2) % STGS_, kc + 2); CPCOMMIT();
            CPWAIT(2);
        } else {
            CPWAIT(0);
        }
        __syncthreads();

        const uint32_t aS = sbase + (kc % STGS_) * STAGE_;
        const uint32_t bS = aS + 8192;
#pragma unroll
        for (int ks = 0; ks < 2; ks++) {
            uint32_t afr[2][4];
#pragma unroll
            for (int mt = 0; mt < 2; mt++) {
                int row = wm * 32 + mt * 16 + ((lane >> 3) & 1) * 8 + (lane & 7);
                int ch  = ks * 2 + (lane >> 4);
                ldsm_x4(afr[mt][0], afr[mt][1], afr[mt][2], afr[mt][3],
                        aS + swz(row, ch));
            }
            uint32_t bfr[8][2];
#pragma unroll
            for (int p = 0; p < 4; p++) {
                int row = wn * 64 + p * 16 + (lane >> 4) * 8 + (lane & 7);
                int ch  = ks * 2 + ((lane >> 3) & 1);
                uint32_t r0, r1, r2, r3;
                ldsm_x4(r0, r1, r2, r3, bS + swz(row, ch));
                bfr[2 * p][0] = r0; bfr[2 * p][1] = r1;
                bfr[2 * p + 1][0] = r2; bfr[2 * p + 1][1] = r3;
            }
#pragma unroll
            for (int mt = 0; mt < 2; mt++)
#pragma unroll
                for (int nt = 0; nt < 8; nt++)
                    mma_bf16(acc[mt][nt], afr[mt], bfr[nt]);
        }
        __syncthreads();
    }

    const float gamma = __ldg(gammaP);
    const int gr = lane >> 2;
    const int qc = (lane & 3) * 2;
#pragma unroll
    for (int mt = 0; mt < 2; mt++) {
#pragma unroll
        for (int rr = 0; rr < 2; rr++) {
            int m    = mBase + wm * 32 + mt * 16 + rr * 8 + gr;
            int hr   = m >> 8;
            int wpix = m & 255;
#pragma unroll
            for (int nt = 0; nt < 8; nt++) {
                int cg = cBase + wn * 64 + nt * 8 + qc;
                int sg = cg >> 8;
                int ch = cg & 255;
                int hh = sg * HS_ + hr;
                size_t idx = (((size_t)b * H_ + hh) * W_ + wpix) * C_ + ch;
                float2 xv = *reinterpret_cast<const float2*>(x + idx);
                float2 o;
                o.x = fmaf(gamma, acc[mt][nt][rr * 2 + 0], xv.x);
                o.y = fmaf(gamma, acc[mt][nt][rr * 2 + 1], xv.y);
                *reinterpret_cast<float2*>(out + idx) = o;
            }
        }
    }
}

// ---------------------------------------------------------------------------
extern "C" void kernel_launch(void* const* d_in, const int* in_sizes, int n_in,
                              void* d_out, int out_size)
{
    const float* x     = (const float*)d_in[0];
    const float* Wf    = (const float*)d_in[1];
    const float* Wg    = (const float*)d_in[2];
    const float* Wh    = (const float*)d_in[3];
    const float* gamma = (const float*)d_in[4];
    float* out = (float*)d_out;

    static bool attrSet = false;
    if (!attrSet) {
        cudaFuncSetAttribute(k_proj_mma, cudaFuncAttributeMaxDynamicSharedMemorySize,
                             PJ_STGS * PJ_STAGE);
        cudaFuncSetAttribute(k_score_mma, cudaFuncAttributeMaxDynamicSharedMemorySize,
                             4 * SC_BUF);
        attrSet = true;
    }

    k_split_x    <<<P_ * C_ / 4 / 256, 256>>>(x);
    k_split_w    <<<320, 256>>>(Wf, Wg, Wh);
    k_proj_mma   <<<dim3(5, P_ / 128), 256, PJ_STGS * PJ_STAGE>>>();
    k_transpose_h<<<dim3(N_ / 32, HC_ / 32, B_), 256>>>();
    k_score_mma  <<<dim3(N_ / 128, N_ / 128, B_), 256, 4 * SC_BUF>>>();
    k_softmax    <<<dim3(B_ * N_), 256>>>();
    k_o_mma      <<<dim3(HC_ / 128, N_ / 128, B_), 256>>>(x, gamma, out);
}